// round 15
// baseline (speedup 1.0000x reference)
#include <cuda_runtime.h>
#include <cstddef>

#define BATCH   4
#define HEADS   8
#define DH      64
#define NSEQ    1600            // H*W = 40*40
#define CIN     512
#define MROWS   (BATCH*NSEQ)    // 6400
#define OQK     1024            // q (512) + k (512) output columns

// Scratch: rope'd q (pre-scaled by dh^-0.5) and k, layout [b][head][n][d]
__device__ float g_q[BATCH*HEADS*NSEQ*DH];
__device__ float g_k[BATCH*HEADS*NSEQ*DH];

// ---------------------------------------------------------------------------
// Kernel 1: qk = x @ w_qkv^T (first 1024 cols only) + bias, then theta-shift
// (rope) and scatter to g_q / g_k. Tile: 128(M) x 64(O), TK=32.
// 256 threads: ty=tid/8 (0..31, 4 rows each), tx=tid%8 (8 cols each).
// ---------------------------------------------------------------------------
__global__ void __launch_bounds__(256) qk_proj_kernel(
    const float* __restrict__ x, const float* __restrict__ w,
    const float* __restrict__ bias,
    const float* __restrict__ sinp, const float* __restrict__ cosp)
{
    __shared__ float As[32][132];   // [kk][m-row], transposed A tile
    __shared__ float Bs[32][68];    // [kk][o-col], transposed B tile

    const int tid = threadIdx.x;
    const int ty = tid >> 3;        // 0..31
    const int tx = tid & 7;         // 0..7
    const int m0 = blockIdx.x * 128;
    const int o0 = blockIdx.y * 64;

    float acc[4][8];
#pragma unroll
    for (int i = 0; i < 4; i++)
#pragma unroll
        for (int j = 0; j < 8; j++) acc[i][j] = 0.f;

    for (int c0 = 0; c0 < CIN; c0 += 32) {
        __syncthreads();
        // A tile: 128 rows x 32 cols = 1024 float4, 4 per thread
#pragma unroll
        for (int it = 0; it < 4; it++) {
            int idx = tid + it * 256;
            int r = idx >> 3, c4 = idx & 7;
            float4 v = *(const float4*)(x + (size_t)(m0 + r) * CIN + c0 + c4 * 4);
            As[c4*4+0][r] = v.x; As[c4*4+1][r] = v.y;
            As[c4*4+2][r] = v.z; As[c4*4+3][r] = v.w;
        }
        // B tile: 64 rows x 32 cols = 512 float4, 2 per thread
#pragma unroll
        for (int it = 0; it < 2; it++) {
            int idx = tid + it * 256;
            int r = idx >> 3, c4 = idx & 7;
            float4 v = *(const float4*)(w + (size_t)(o0 + r) * CIN + c0 + c4 * 4);
            Bs[c4*4+0][r] = v.x; Bs[c4*4+1][r] = v.y;
            Bs[c4*4+2][r] = v.z; Bs[c4*4+3][r] = v.w;
        }
        __syncthreads();
#pragma unroll 8
        for (int kk = 0; kk < 32; kk++) {
            float4 a4 = *(const float4*)&As[kk][ty*4];
            float4 b0 = *(const float4*)&Bs[kk][tx*8];
            float4 b1 = *(const float4*)&Bs[kk][tx*8+4];
            float a[4] = {a4.x, a4.y, a4.z, a4.w};
            float b[8] = {b0.x, b0.y, b0.z, b0.w, b1.x, b1.y, b1.z, b1.w};
#pragma unroll
            for (int i = 0; i < 4; i++)
#pragma unroll
                for (int j = 0; j < 8; j++)
                    acc[i][j] = fmaf(a[i], b[j], acc[i][j]);
        }
    }

    // Epilogue: bias + rope + scatter.  All 8 cols of a thread share one head.
    const int o_base = o0 + tx * 8;
    const bool is_q = (o_base < 512);
    const int head  = (o_base >> 6) & 7;
    const int d0    = o_base & 63;
    float bv[8];
#pragma unroll
    for (int j = 0; j < 8; j++) bv[j] = bias[o_base + j];
    const float qscale = 0.125f;    // dh^-0.5

#pragma unroll
    for (int i = 0; i < 4; i++) {
        int m = m0 + ty * 4 + i;
        int bb = m / NSEQ;
        int n  = m - bb * NSEQ;
        const float* sp = sinp + (size_t)n * DH + d0;
        const float* cp = cosp + (size_t)n * DH + d0;
        float4 s01 = *(const float4*)sp,  s23 = *(const float4*)(sp + 4);
        float4 c01 = *(const float4*)cp,  c23 = *(const float4*)(cp + 4);
        float sn[8] = {s01.x, s01.y, s01.z, s01.w, s23.x, s23.y, s23.z, s23.w};
        float cs[8] = {c01.x, c01.y, c01.z, c01.w, c23.x, c23.y, c23.z, c23.w};
        float r[8];
#pragma unroll
        for (int p = 0; p < 4; p++) {
            float v0 = acc[i][2*p]   + bv[2*p];
            float v1 = acc[i][2*p+1] + bv[2*p+1];
            r[2*p]   = v0 * cs[2*p]   - v1 * sn[2*p];
            r[2*p+1] = v1 * cs[2*p+1] + v0 * sn[2*p+1];
        }
        if (is_q) {
#pragma unroll
            for (int j = 0; j < 8; j++) r[j] *= qscale;
        }
        float* dst = (is_q ? g_q : g_k)
                   + (((size_t)(bb * HEADS + head) * NSEQ + n) * DH + d0);
        *(float4*)(dst)     = make_float4(r[0], r[1], r[2], r[3]);
        *(float4*)(dst + 4) = make_float4(r[4], r[5], r[6], r[7]);
    }
}

// ---------------------------------------------------------------------------
// Kernel 2: flash attention per (b,h).  CTA = 64 query rows; loop over 25
// key tiles of 64.  out = softmax(q k^T) @ k.  128 threads:
// ty=tid/8 (0..15, 4 rows), tx=tid%8 (8 cols).  Dynamic smem 69632 B.
// ---------------------------------------------------------------------------
#define ATTN_SMEM (4 * 64 * 68 * 4)

__global__ void __launch_bounds__(128) attn_kernel(float* __restrict__ out)
{
    extern __shared__ float sm[];
    float* qs  = sm;                 // [d][r]   stride 68
    float* ks  = sm + 64 * 68;       // [n][d]   stride 68
    float* kst = sm + 2 * 64 * 68;   // [d][n]   stride 68
    float* ps  = sm + 3 * 64 * 68;   // [n][r]   stride 68

    const int tid = threadIdx.x;
    const int ty = tid >> 3;         // 0..15
    const int tx = tid & 7;          // 0..7
    const int bh = blockIdx.y;
    const int b = bh >> 3, h = bh & 7;
    const int m0 = blockIdx.x * 64;

    const float* qg = g_q + ((size_t)bh * NSEQ + m0) * DH;
    const float* kg = g_k + (size_t)bh * NSEQ * DH;

    // Load q block transposed into qs[d][r]: 64x16 float4, 8 per thread
#pragma unroll
    for (int it = 0; it < 8; it++) {
        int idx = tid + it * 128;
        int r = idx >> 4, c4 = idx & 15;
        float4 v = *(const float4*)(qg + (size_t)r * DH + c4 * 4);
        qs[(c4*4+0)*68 + r] = v.x; qs[(c4*4+1)*68 + r] = v.y;
        qs[(c4*4+2)*68 + r] = v.z; qs[(c4*4+3)*68 + r] = v.w;
    }

    float m_i[4], l_i[4], o_acc[4][8];
#pragma unroll
    for (int i = 0; i < 4; i++) {
        m_i[i] = -1e30f; l_i[i] = 0.f;
#pragma unroll
        for (int j = 0; j < 8; j++) o_acc[i][j] = 0.f;
    }

    for (int n0 = 0; n0 < NSEQ; n0 += 64) {
        __syncthreads();   // also covers the initial q-load
        // K tile into both orientations
#pragma unroll
        for (int it = 0; it < 8; it++) {
            int idx = tid + it * 128;
            int r = idx >> 4, c4 = idx & 15;
            float4 v = *(const float4*)(kg + (size_t)(n0 + r) * DH + c4 * 4);
            *(float4*)&ks[r*68 + c4*4] = v;
            kst[(c4*4+0)*68 + r] = v.x; kst[(c4*4+1)*68 + r] = v.y;
            kst[(c4*4+2)*68 + r] = v.z; kst[(c4*4+3)*68 + r] = v.w;
        }
        __syncthreads();

        // S = q @ k^T  (q pre-scaled)
        float s[4][8];
#pragma unroll
        for (int i = 0; i < 4; i++)
#pragma unroll
            for (int j = 0; j < 8; j++) s[i][j] = 0.f;
#pragma unroll 8
        for (int kk = 0; kk < 64; kk++) {
            float4 a4 = *(const float4*)&qs[kk*68 + ty*4];
            float4 b0 = *(const float4*)&kst[kk*68 + tx*8];
            float4 b1 = *(const float4*)&kst[kk*68 + tx*8+4];
            float a[4] = {a4.x, a4.y, a4.z, a4.w};
            float bb2[8] = {b0.x, b0.y, b0.z, b0.w, b1.x, b1.y, b1.z, b1.w};
#pragma unroll
            for (int i = 0; i < 4; i++)
#pragma unroll
                for (int j = 0; j < 8; j++)
                    s[i][j] = fmaf(a[i], bb2[j], s[i][j]);
        }

        // Online softmax (row owned by 8 lanes sharing ty; shfl over tx bits)
#pragma unroll
        for (int i = 0; i < 4; i++) {
            float mx = s[i][0];
#pragma unroll
            for (int j = 1; j < 8; j++) mx = fmaxf(mx, s[i][j]);
            mx = fmaxf(mx, __shfl_xor_sync(0xffffffffu, mx, 1));
            mx = fmaxf(mx, __shfl_xor_sync(0xffffffffu, mx, 2));
            mx = fmaxf(mx, __shfl_xor_sync(0xffffffffu, mx, 4));
            float mnew = fmaxf(m_i[i], mx);
            float alpha = __expf(m_i[i] - mnew);
            m_i[i] = mnew;
            float rs = 0.f;
#pragma unroll
            for (int j = 0; j < 8; j++) {
                s[i][j] = __expf(s[i][j] - mnew);
                rs += s[i][j];
            }
            rs += __shfl_xor_sync(0xffffffffu, rs, 1);
            rs += __shfl_xor_sync(0xffffffffu, rs, 2);
            rs += __shfl_xor_sync(0xffffffffu, rs, 4);
            l_i[i] = l_i[i] * alpha + rs;
#pragma unroll
            for (int j = 0; j < 8; j++) o_acc[i][j] *= alpha;
        }

        // Store P transposed: ps[n][r]
#pragma unroll
        for (int j = 0; j < 8; j++)
#pragma unroll
            for (int i = 0; i < 4; i++)
                ps[(tx*8+j)*68 + ty*4+i] = s[i][j];
        __syncthreads();

        // O += P @ K
#pragma unroll 8
        for (int kk = 0; kk < 64; kk++) {
            float4 a4 = *(const float4*)&ps[kk*68 + ty*4];
            float4 b0 = *(const float4*)&ks[kk*68 + tx*8];
            float4 b1 = *(const float4*)&ks[kk*68 + tx*8+4];
            float a[4] = {a4.x, a4.y, a4.z, a4.w};
            float bb2[8] = {b0.x, b0.y, b0.z, b0.w, b1.x, b1.y, b1.z, b1.w};
#pragma unroll
            for (int i = 0; i < 4; i++)
#pragma unroll
                for (int j = 0; j < 8; j++)
                    o_acc[i][j] = fmaf(a[i], bb2[j], o_acc[i][j]);
        }
    }

    // Write out: out[b][n][head*64 + d]
#pragma unroll
    for (int i = 0; i < 4; i++) {
        float inv = 1.0f / l_i[i];
        int r = m0 + ty * 4 + i;
        float* dst = out + ((size_t)b * NSEQ + r) * (HEADS * DH) + h * DH + tx * 8;
        *(float4*)(dst)     = make_float4(o_acc[i][0]*inv, o_acc[i][1]*inv,
                                          o_acc[i][2]*inv, o_acc[i][3]*inv);
        *(float4*)(dst + 4) = make_float4(o_acc[i][4]*inv, o_acc[i][5]*inv,
                                          o_acc[i][6]*inv, o_acc[i][7]*inv);
    }
}

// ---------------------------------------------------------------------------
extern "C" void kernel_launch(void* const* d_in, const int* in_sizes, int n_in,
                              void* d_out, int out_size)
{
    (void)in_sizes; (void)n_in; (void)out_size;
    const float* x    = (const float*)d_in[0];
    const float* sinp = (const float*)d_in[1];
    const float* cosp = (const float*)d_in[2];
    const float* wqkv = (const float*)d_in[3];
    const float* bqkv = (const float*)d_in[4];
    float* out = (float*)d_out;

    cudaFuncSetAttribute(attn_kernel,
                         cudaFuncAttributeMaxDynamicSharedMemorySize, ATTN_SMEM);

    dim3 g1(MROWS / 128, OQK / 64);   // (50, 16)
    qk_proj_kernel<<<g1, 256>>>(x, wqkv, bqkv, sinp, cosp);

    dim3 g2(NSEQ / 64, BATCH * HEADS); // (25, 32)
    attn_kernel<<<g2, 128, ATTN_SMEM>>>(out);
}

// round 16
// speedup vs baseline: 1.0002x; 1.0002x over previous
#include <cuda_runtime.h>
#include <cstddef>

#define BATCH   4
#define HEADS   8
#define DH      64
#define NSEQ    1600            // H*W = 40*40
#define CIN     512
#define MROWS   (BATCH*NSEQ)    // 6400
#define OQK     1024            // q (512) + k (512) output columns

// Scratch: rope'd q (pre-scaled by dh^-0.5) and k, layout [b][head][n][d]
__device__ float g_q[BATCH*HEADS*NSEQ*DH];
__device__ float g_k[BATCH*HEADS*NSEQ*DH];

// ---------------------------------------------------------------------------
// Kernel 1: qk = x @ w_qkv^T (first 1024 cols only) + bias, then theta-shift
// (rope) and scatter to g_q / g_k. Tile: 128(M) x 64(O), TK=32.
// 256 threads: ty=tid/8 (0..31, 4 rows each), tx=tid%8 (8 cols each).
// ---------------------------------------------------------------------------
__global__ void __launch_bounds__(256) qk_proj_kernel(
    const float* __restrict__ x, const float* __restrict__ w,
    const float* __restrict__ bias,
    const float* __restrict__ sinp, const float* __restrict__ cosp)
{
    __shared__ float As[32][132];   // [kk][m-row], transposed A tile
    __shared__ float Bs[32][68];    // [kk][o-col], transposed B tile

    const int tid = threadIdx.x;
    const int ty = tid >> 3;        // 0..31
    const int tx = tid & 7;         // 0..7
    const int m0 = blockIdx.x * 128;
    const int o0 = blockIdx.y * 64;

    float acc[4][8];
#pragma unroll
    for (int i = 0; i < 4; i++)
#pragma unroll
        for (int j = 0; j < 8; j++) acc[i][j] = 0.f;

    for (int c0 = 0; c0 < CIN; c0 += 32) {
        __syncthreads();
        // A tile: 128 rows x 32 cols = 1024 float4, 4 per thread
#pragma unroll
        for (int it = 0; it < 4; it++) {
            int idx = tid + it * 256;
            int r = idx >> 3, c4 = idx & 7;
            float4 v = *(const float4*)(x + (size_t)(m0 + r) * CIN + c0 + c4 * 4);
            As[c4*4+0][r] = v.x; As[c4*4+1][r] = v.y;
            As[c4*4+2][r] = v.z; As[c4*4+3][r] = v.w;
        }
        // B tile: 64 rows x 32 cols = 512 float4, 2 per thread
#pragma unroll
        for (int it = 0; it < 2; it++) {
            int idx = tid + it * 256;
            int r = idx >> 3, c4 = idx & 7;
            float4 v = *(const float4*)(w + (size_t)(o0 + r) * CIN + c0 + c4 * 4);
            Bs[c4*4+0][r] = v.x; Bs[c4*4+1][r] = v.y;
            Bs[c4*4+2][r] = v.z; Bs[c4*4+3][r] = v.w;
        }
        __syncthreads();
#pragma unroll 8
        for (int kk = 0; kk < 32; kk++) {
            float4 a4 = *(const float4*)&As[kk][ty*4];
            float4 b0 = *(const float4*)&Bs[kk][tx*8];
            float4 b1 = *(const float4*)&Bs[kk][tx*8+4];
            float a[4] = {a4.x, a4.y, a4.z, a4.w};
            float b[8] = {b0.x, b0.y, b0.z, b0.w, b1.x, b1.y, b1.z, b1.w};
#pragma unroll
            for (int i = 0; i < 4; i++)
#pragma unroll
                for (int j = 0; j < 8; j++)
                    acc[i][j] = fmaf(a[i], b[j], acc[i][j]);
        }
    }

    // Epilogue: bias + rope + scatter.  All 8 cols of a thread share one head.
    const int o_base = o0 + tx * 8;
    const bool is_q = (o_base < 512);
    const int head  = (o_base >> 6) & 7;
    const int d0    = o_base & 63;
    float bv[8];
#pragma unroll
    for (int j = 0; j < 8; j++) bv[j] = bias[o_base + j];
    const float qscale = 0.125f;    // dh^-0.5

#pragma unroll
    for (int i = 0; i < 4; i++) {
        int m = m0 + ty * 4 + i;
        int bb = m / NSEQ;
        int n  = m - bb * NSEQ;
        const float* sp = sinp + (size_t)n * DH + d0;
        const float* cp = cosp + (size_t)n * DH + d0;
        float4 s01 = *(const float4*)sp,  s23 = *(const float4*)(sp + 4);
        float4 c01 = *(const float4*)cp,  c23 = *(const float4*)(cp + 4);
        float sn[8] = {s01.x, s01.y, s01.z, s01.w, s23.x, s23.y, s23.z, s23.w};
        float cs[8] = {c01.x, c01.y, c01.z, c01.w, c23.x, c23.y, c23.z, c23.w};
        float r[8];
#pragma unroll
        for (int p = 0; p < 4; p++) {
            float v0 = acc[i][2*p]   + bv[2*p];
            float v1 = acc[i][2*p+1] + bv[2*p+1];
            r[2*p]   = v0 * cs[2*p]   - v1 * sn[2*p];
            r[2*p+1] = v1 * cs[2*p+1] + v0 * sn[2*p+1];
        }
        if (is_q) {
#pragma unroll
            for (int j = 0; j < 8; j++) r[j] *= qscale;
        }
        float* dst = (is_q ? g_q : g_k)
                   + (((size_t)(bb * HEADS + head) * NSEQ + n) * DH + d0);
        *(float4*)(dst)     = make_float4(r[0], r[1], r[2], r[3]);
        *(float4*)(dst + 4) = make_float4(r[4], r[5], r[6], r[7]);
    }
}

// ---------------------------------------------------------------------------
// Kernel 2: flash attention per (b,h).  CTA = 64 query rows; loop over 25
// key tiles of 64.  out = softmax(q k^T) @ k.  128 threads:
// ty=tid/8 (0..15, 4 rows), tx=tid%8 (8 cols).  Dynamic smem 69632 B.
// ---------------------------------------------------------------------------
#define ATTN_SMEM (4 * 64 * 68 * 4)

__global__ void __launch_bounds__(128) attn_kernel(float* __restrict__ out)
{
    extern __shared__ float sm[];
    float* qs  = sm;                 // [d][r]   stride 68
    float* ks  = sm + 64 * 68;       // [n][d]   stride 68
    float* kst = sm + 2 * 64 * 68;   // [d][n]   stride 68
    float* ps  = sm + 3 * 64 * 68;   // [n][r]   stride 68

    const int tid = threadIdx.x;
    const int ty = tid >> 3;         // 0..15
    const int tx = tid & 7;          // 0..7
    const int bh = blockIdx.y;
    const int b = bh >> 3, h = bh & 7;
    const int m0 = blockIdx.x * 64;

    const float* qg = g_q + ((size_t)bh * NSEQ + m0) * DH;
    const float* kg = g_k + (size_t)bh * NSEQ * DH;

    // Load q block transposed into qs[d][r]: 64x16 float4, 8 per thread
#pragma unroll
    for (int it = 0; it < 8; it++) {
        int idx = tid + it * 128;
        int r = idx >> 4, c4 = idx & 15;
        float4 v = *(const float4*)(qg + (size_t)r * DH + c4 * 4);
        qs[(c4*4+0)*68 + r] = v.x; qs[(c4*4+1)*68 + r] = v.y;
        qs[(c4*4+2)*68 + r] = v.z; qs[(c4*4+3)*68 + r] = v.w;
    }

    float m_i[4], l_i[4], o_acc[4][8];
#pragma unroll
    for (int i = 0; i < 4; i++) {
        m_i[i] = -1e30f; l_i[i] = 0.f;
#pragma unroll
        for (int j = 0; j < 8; j++) o_acc[i][j] = 0.f;
    }

    for (int n0 = 0; n0 < NSEQ; n0 += 64) {
        __syncthreads();   // also covers the initial q-load
        // K tile into both orientations
#pragma unroll
        for (int it = 0; it < 8; it++) {
            int idx = tid + it * 128;
            int r = idx >> 4, c4 = idx & 15;
            float4 v = *(const float4*)(kg + (size_t)(n0 + r) * DH + c4 * 4);
            *(float4*)&ks[r*68 + c4*4] = v;
            kst[(c4*4+0)*68 + r] = v.x; kst[(c4*4+1)*68 + r] = v.y;
            kst[(c4*4+2)*68 + r] = v.z; kst[(c4*4+3)*68 + r] = v.w;
        }
        __syncthreads();

        // S = q @ k^T  (q pre-scaled)
        float s[4][8];
#pragma unroll
        for (int i = 0; i < 4; i++)
#pragma unroll
            for (int j = 0; j < 8; j++) s[i][j] = 0.f;
#pragma unroll 8
        for (int kk = 0; kk < 64; kk++) {
            float4 a4 = *(const float4*)&qs[kk*68 + ty*4];
            float4 b0 = *(const float4*)&kst[kk*68 + tx*8];
            float4 b1 = *(const float4*)&kst[kk*68 + tx*8+4];
            float a[4] = {a4.x, a4.y, a4.z, a4.w};
            float bb2[8] = {b0.x, b0.y, b0.z, b0.w, b1.x, b1.y, b1.z, b1.w};
#pragma unroll
            for (int i = 0; i < 4; i++)
#pragma unroll
                for (int j = 0; j < 8; j++)
                    s[i][j] = fmaf(a[i], bb2[j], s[i][j]);
        }

        // Online softmax (row owned by 8 lanes sharing ty; shfl over tx bits)
#pragma unroll
        for (int i = 0; i < 4; i++) {
            float mx = s[i][0];
#pragma unroll
            for (int j = 1; j < 8; j++) mx = fmaxf(mx, s[i][j]);
            mx = fmaxf(mx, __shfl_xor_sync(0xffffffffu, mx, 1));
            mx = fmaxf(mx, __shfl_xor_sync(0xffffffffu, mx, 2));
            mx = fmaxf(mx, __shfl_xor_sync(0xffffffffu, mx, 4));
            float mnew = fmaxf(m_i[i], mx);
            float alpha = __expf(m_i[i] - mnew);
            m_i[i] = mnew;
            float rs = 0.f;
#pragma unroll
            for (int j = 0; j < 8; j++) {
                s[i][j] = __expf(s[i][j] - mnew);
                rs += s[i][j];
            }
            rs += __shfl_xor_sync(0xffffffffu, rs, 1);
            rs += __shfl_xor_sync(0xffffffffu, rs, 2);
            rs += __shfl_xor_sync(0xffffffffu, rs, 4);
            l_i[i] = l_i[i] * alpha + rs;
#pragma unroll
            for (int j = 0; j < 8; j++) o_acc[i][j] *= alpha;
        }

        // Store P transposed: ps[n][r]
#pragma unroll
        for (int j = 0; j < 8; j++)
#pragma unroll
            for (int i = 0; i < 4; i++)
                ps[(tx*8+j)*68 + ty*4+i] = s[i][j];
        __syncthreads();

        // O += P @ K
#pragma unroll 8
        for (int kk = 0; kk < 64; kk++) {
            float4 a4 = *(const float4*)&ps[kk*68 + ty*4];
            float4 b0 = *(const float4*)&ks[kk*68 + tx*8];
            float4 b1 = *(const float4*)&ks[kk*68 + tx*8+4];
            float a[4] = {a4.x, a4.y, a4.z, a4.w};
            float bb2[8] = {b0.x, b0.y, b0.z, b0.w, b1.x, b1.y, b1.z, b1.w};
#pragma unroll
            for (int i = 0; i < 4; i++)
#pragma unroll
                for (int j = 0; j < 8; j++)
                    o_acc[i][j] = fmaf(a[i], bb2[j], o_acc[i][j]);
        }
    }

    // Write out: out[b][n][head*64 + d]
#pragma unroll
    for (int i = 0; i < 4; i++) {
        float inv = 1.0f / l_i[i];
        int r = m0 + ty * 4 + i;
        float* dst = out + ((size_t)b * NSEQ + r) * (HEADS * DH) + h * DH + tx * 8;
        *(float4*)(dst)     = make_float4(o_acc[i][0]*inv, o_acc[i][1]*inv,
                                          o_acc[i][2]*inv, o_acc[i][3]*inv);
        *(float4*)(dst + 4) = make_float4(o_acc[i][4]*inv, o_acc[i][5]*inv,
                                          o_acc[i][6]*inv, o_acc[i][7]*inv);
    }
}

// ---------------------------------------------------------------------------
extern "C" void kernel_launch(void* const* d_in, const int* in_sizes, int n_in,
                              void* d_out, int out_size)
{
    (void)in_sizes; (void)n_in; (void)out_size;
    const float* x    = (const float*)d_in[0];
    const float* sinp = (const float*)d_in[1];
    const float* cosp = (const float*)d_in[2];
    const float* wqkv = (const float*)d_in[3];
    const float* bqkv = (const float*)d_in[4];
    float* out = (float*)d_out;

    cudaFuncSetAttribute(attn_kernel,
                         cudaFuncAttributeMaxDynamicSharedMemorySize, ATTN_SMEM);

    dim3 g1(MROWS / 128, OQK / 64);   // (50, 16)
    qk_proj_kernel<<<g1, 256>>>(x, wqkv, bqkv, sinp, cosp);

    dim3 g2(NSEQ / 64, BATCH * HEADS); // (25, 32)
    attn_kernel<<<g2, 128, ATTN_SMEM>>>(out);
}

// round 17
// speedup vs baseline: 1.0014x; 1.0012x over previous
#include <cuda_runtime.h>
#include <cstddef>

#define BATCH   4
#define HEADS   8
#define DH      64
#define NSEQ    1600            // H*W = 40*40
#define CIN     512
#define MROWS   (BATCH*NSEQ)    // 6400
#define OQK     1024            // q (512) + k (512) output columns

// Scratch: rope'd q (pre-scaled by dh^-0.5) and k, layout [b][head][n][d]
__device__ float g_q[BATCH*HEADS*NSEQ*DH];
__device__ float g_k[BATCH*HEADS*NSEQ*DH];

// ---------------------------------------------------------------------------
// Kernel 1: qk = x @ w_qkv^T (first 1024 cols only) + bias, then theta-shift
// (rope) and scatter to g_q / g_k. Tile: 128(M) x 64(O), TK=32.
// 256 threads: ty=tid/8 (0..31, 4 rows each), tx=tid%8 (8 cols each).
// ---------------------------------------------------------------------------
__global__ void __launch_bounds__(256) qk_proj_kernel(
    const float* __restrict__ x, const float* __restrict__ w,
    const float* __restrict__ bias,
    const float* __restrict__ sinp, const float* __restrict__ cosp)
{
    __shared__ float As[32][132];   // [kk][m-row], transposed A tile
    __shared__ float Bs[32][68];    // [kk][o-col], transposed B tile

    const int tid = threadIdx.x;
    const int ty = tid >> 3;        // 0..31
    const int tx = tid & 7;         // 0..7
    const int m0 = blockIdx.x * 128;
    const int o0 = blockIdx.y * 64;

    float acc[4][8];
#pragma unroll
    for (int i = 0; i < 4; i++)
#pragma unroll
        for (int j = 0; j < 8; j++) acc[i][j] = 0.f;

    for (int c0 = 0; c0 < CIN; c0 += 32) {
        __syncthreads();
        // A tile: 128 rows x 32 cols = 1024 float4, 4 per thread
#pragma unroll
        for (int it = 0; it < 4; it++) {
            int idx = tid + it * 256;
            int r = idx >> 3, c4 = idx & 7;
            float4 v = *(const float4*)(x + (size_t)(m0 + r) * CIN + c0 + c4 * 4);
            As[c4*4+0][r] = v.x; As[c4*4+1][r] = v.y;
            As[c4*4+2][r] = v.z; As[c4*4+3][r] = v.w;
        }
        // B tile: 64 rows x 32 cols = 512 float4, 2 per thread
#pragma unroll
        for (int it = 0; it < 2; it++) {
            int idx = tid + it * 256;
            int r = idx >> 3, c4 = idx & 7;
            float4 v = *(const float4*)(w + (size_t)(o0 + r) * CIN + c0 + c4 * 4);
            Bs[c4*4+0][r] = v.x; Bs[c4*4+1][r] = v.y;
            Bs[c4*4+2][r] = v.z; Bs[c4*4+3][r] = v.w;
        }
        __syncthreads();
#pragma unroll 8
        for (int kk = 0; kk < 32; kk++) {
            float4 a4 = *(const float4*)&As[kk][ty*4];
            float4 b0 = *(const float4*)&Bs[kk][tx*8];
            float4 b1 = *(const float4*)&Bs[kk][tx*8+4];
            float a[4] = {a4.x, a4.y, a4.z, a4.w};
            float b[8] = {b0.x, b0.y, b0.z, b0.w, b1.x, b1.y, b1.z, b1.w};
#pragma unroll
            for (int i = 0; i < 4; i++)
#pragma unroll
                for (int j = 0; j < 8; j++)
                    acc[i][j] = fmaf(a[i], b[j], acc[i][j]);
        }
    }

    // Epilogue: bias + rope + scatter.  All 8 cols of a thread share one head.
    const int o_base = o0 + tx * 8;
    const bool is_q = (o_base < 512);
    const int head  = (o_base >> 6) & 7;
    const int d0    = o_base & 63;
    float bv[8];
#pragma unroll
    for (int j = 0; j < 8; j++) bv[j] = bias[o_base + j];
    const float qscale = 0.125f;    // dh^-0.5

#pragma unroll
    for (int i = 0; i < 4; i++) {
        int m = m0 + ty * 4 + i;
        int bb = m / NSEQ;
        int n  = m - bb * NSEQ;
        const float* sp = sinp + (size_t)n * DH + d0;
        const float* cp = cosp + (size_t)n * DH + d0;
        float4 s01 = *(const float4*)sp,  s23 = *(const float4*)(sp + 4);
        float4 c01 = *(const float4*)cp,  c23 = *(const float4*)(cp + 4);
        float sn[8] = {s01.x, s01.y, s01.z, s01.w, s23.x, s23.y, s23.z, s23.w};
        float cs[8] = {c01.x, c01.y, c01.z, c01.w, c23.x, c23.y, c23.z, c23.w};
        float r[8];
#pragma unroll
        for (int p = 0; p < 4; p++) {
            float v0 = acc[i][2*p]   + bv[2*p];
            float v1 = acc[i][2*p+1] + bv[2*p+1];
            r[2*p]   = v0 * cs[2*p]   - v1 * sn[2*p];
            r[2*p+1] = v1 * cs[2*p+1] + v0 * sn[2*p+1];
        }
        if (is_q) {
#pragma unroll
            for (int j = 0; j < 8; j++) r[j] *= qscale;
        }
        float* dst = (is_q ? g_q : g_k)
                   + (((size_t)(bb * HEADS + head) * NSEQ + n) * DH + d0);
        *(float4*)(dst)     = make_float4(r[0], r[1], r[2], r[3]);
        *(float4*)(dst + 4) = make_float4(r[4], r[5], r[6], r[7]);
    }
}

// ---------------------------------------------------------------------------
// Kernel 2: flash attention per (b,h).  CTA = 64 query rows; loop over 25
// key tiles of 64.  out = softmax(q k^T) @ k.  128 threads:
// ty=tid/8 (0..15, 4 rows), tx=tid%8 (8 cols).  Dynamic smem 69632 B.
// ---------------------------------------------------------------------------
#define ATTN_SMEM (4 * 64 * 68 * 4)

__global__ void __launch_bounds__(128) attn_kernel(float* __restrict__ out)
{
    extern __shared__ float sm[];
    float* qs  = sm;                 // [d][r]   stride 68
    float* ks  = sm + 64 * 68;       // [n][d]   stride 68
    float* kst = sm + 2 * 64 * 68;   // [d][n]   stride 68
    float* ps  = sm + 3 * 64 * 68;   // [n][r]   stride 68

    const int tid = threadIdx.x;
    const int ty = tid >> 3;         // 0..15
    const int tx = tid & 7;          // 0..7
    const int bh = blockIdx.y;
    const int b = bh >> 3, h = bh & 7;
    const int m0 = blockIdx.x * 64;

    const float* qg = g_q + ((size_t)bh * NSEQ + m0) * DH;
    const float* kg = g_k + (size_t)bh * NSEQ * DH;

    // Load q block transposed into qs[d][r]: 64x16 float4, 8 per thread
#pragma unroll
    for (int it = 0; it < 8; it++) {
        int idx = tid + it * 128;
        int r = idx >> 4, c4 = idx & 15;
        float4 v = *(const float4*)(qg + (size_t)r * DH + c4 * 4);
        qs[(c4*4+0)*68 + r] = v.x; qs[(c4*4+1)*68 + r] = v.y;
        qs[(c4*4+2)*68 + r] = v.z; qs[(c4*4+3)*68 + r] = v.w;
    }

    float m_i[4], l_i[4], o_acc[4][8];
#pragma unroll
    for (int i = 0; i < 4; i++) {
        m_i[i] = -1e30f; l_i[i] = 0.f;
#pragma unroll
        for (int j = 0; j < 8; j++) o_acc[i][j] = 0.f;
    }

    for (int n0 = 0; n0 < NSEQ; n0 += 64) {
        __syncthreads();   // also covers the initial q-load
        // K tile into both orientations
#pragma unroll
        for (int it = 0; it < 8; it++) {
            int idx = tid + it * 128;
            int r = idx >> 4, c4 = idx & 15;
            float4 v = *(const float4*)(kg + (size_t)(n0 + r) * DH + c4 * 4);
            *(float4*)&ks[r*68 + c4*4] = v;
            kst[(c4*4+0)*68 + r] = v.x; kst[(c4*4+1)*68 + r] = v.y;
            kst[(c4*4+2)*68 + r] = v.z; kst[(c4*4+3)*68 + r] = v.w;
        }
        __syncthreads();

        // S = q @ k^T  (q pre-scaled)
        float s[4][8];
#pragma unroll
        for (int i = 0; i < 4; i++)
#pragma unroll
            for (int j = 0; j < 8; j++) s[i][j] = 0.f;
#pragma unroll 8
        for (int kk = 0; kk < 64; kk++) {
            float4 a4 = *(const float4*)&qs[kk*68 + ty*4];
            float4 b0 = *(const float4*)&kst[kk*68 + tx*8];
            float4 b1 = *(const float4*)&kst[kk*68 + tx*8+4];
            float a[4] = {a4.x, a4.y, a4.z, a4.w};
            float bb2[8] = {b0.x, b0.y, b0.z, b0.w, b1.x, b1.y, b1.z, b1.w};
#pragma unroll
            for (int i = 0; i < 4; i++)
#pragma unroll
                for (int j = 0; j < 8; j++)
                    s[i][j] = fmaf(a[i], bb2[j], s[i][j]);
        }

        // Online softmax (row owned by 8 lanes sharing ty; shfl over tx bits)
#pragma unroll
        for (int i = 0; i < 4; i++) {
            float mx = s[i][0];
#pragma unroll
            for (int j = 1; j < 8; j++) mx = fmaxf(mx, s[i][j]);
            mx = fmaxf(mx, __shfl_xor_sync(0xffffffffu, mx, 1));
            mx = fmaxf(mx, __shfl_xor_sync(0xffffffffu, mx, 2));
            mx = fmaxf(mx, __shfl_xor_sync(0xffffffffu, mx, 4));
            float mnew = fmaxf(m_i[i], mx);
            float alpha = __expf(m_i[i] - mnew);
            m_i[i] = mnew;
            float rs = 0.f;
#pragma unroll
            for (int j = 0; j < 8; j++) {
                s[i][j] = __expf(s[i][j] - mnew);
                rs += s[i][j];
            }
            rs += __shfl_xor_sync(0xffffffffu, rs, 1);
            rs += __shfl_xor_sync(0xffffffffu, rs, 2);
            rs += __shfl_xor_sync(0xffffffffu, rs, 4);
            l_i[i] = l_i[i] * alpha + rs;
#pragma unroll
            for (int j = 0; j < 8; j++) o_acc[i][j] *= alpha;
        }

        // Store P transposed: ps[n][r]
#pragma unroll
        for (int j = 0; j < 8; j++)
#pragma unroll
            for (int i = 0; i < 4; i++)
                ps[(tx*8+j)*68 + ty*4+i] = s[i][j];
        __syncthreads();

        // O += P @ K
#pragma unroll 8
        for (int kk = 0; kk < 64; kk++) {
            float4 a4 = *(const float4*)&ps[kk*68 + ty*4];
            float4 b0 = *(const float4*)&ks[kk*68 + tx*8];
            float4 b1 = *(const float4*)&ks[kk*68 + tx*8+4];
            float a[4] = {a4.x, a4.y, a4.z, a4.w};
            float bb2[8] = {b0.x, b0.y, b0.z, b0.w, b1.x, b1.y, b1.z, b1.w};
#pragma unroll
            for (int i = 0; i < 4; i++)
#pragma unroll
                for (int j = 0; j < 8; j++)
                    o_acc[i][j] = fmaf(a[i], bb2[j], o_acc[i][j]);
        }
    }

    // Write out: out[b][n][head*64 + d]
#pragma unroll
    for (int i = 0; i < 4; i++) {
        float inv = 1.0f / l_i[i];
        int r = m0 + ty * 4 + i;
        float* dst = out + ((size_t)b * NSEQ + r) * (HEADS * DH) + h * DH + tx * 8;
        *(float4*)(dst)     = make_float4(o_acc[i][0]*inv, o_acc[i][1]*inv,
                                          o_acc[i][2]*inv, o_acc[i][3]*inv);
        *(float4*)(dst + 4) = make_float4(o_acc[i][4]*inv, o_acc[i][5]*inv,
                                          o_acc[i][6]*inv, o_acc[i][7]*inv);
    }
}

// ---------------------------------------------------------------------------
extern "C" void kernel_launch(void* const* d_in, const int* in_sizes, int n_in,
                              void* d_out, int out_size)
{
    (void)in_sizes; (void)n_in; (void)out_size;
    const float* x    = (const float*)d_in[0];
    const float* sinp = (const float*)d_in[1];
    const float* cosp = (const float*)d_in[2];
    const float* wqkv = (const float*)d_in[3];
    const float* bqkv = (const float*)d_in[4];
    float* out = (float*)d_out;

    cudaFuncSetAttribute(attn_kernel,
                         cudaFuncAttributeMaxDynamicSharedMemorySize, ATTN_SMEM);

    dim3 g1(MROWS / 128, OQK / 64);   // (50, 16)
    qk_proj_kernel<<<g1, 256>>>(x, wqkv, bqkv, sinp, cosp);

    dim3 g2(NSEQ / 64, BATCH * HEADS); // (25, 32)
    attn_kernel<<<g2, 128, ATTN_SMEM>>>(out);
}